// round 1
// baseline (speedup 1.0000x reference)
#include <cuda_runtime.h>

#define KK 128        // units per node
#define BATCH 256
#define DD 1024       // leaf variables
#define NNODES 1023
#define BK (BATCH*KK)

// static scratch (allocation-free rule: __device__ globals)
__device__ float g_sw[NNODES * KK * KK];      // softmax(weights)
__device__ float g_buf0[512 * BATCH * KK];    // ping
__device__ float g_buf1[256 * BATCH * KK];    // pong

// ---------------- K0: row softmax over weights last dim ----------------
__global__ void softmax_kernel(const float* __restrict__ w) {
    int node = blockIdx.x;
    int warp = threadIdx.x >> 5, lane = threadIdx.x & 31;
    const float* wn = w + (size_t)node * (KK * KK);
    float* sn = g_sw + (size_t)node * (KK * KK);
    for (int r = warp; r < KK; r += 8) {
        float4 v = ((const float4*)(wn + r * KK))[lane];
        float m = fmaxf(fmaxf(v.x, v.y), fmaxf(v.z, v.w));
        #pragma unroll
        for (int o = 16; o; o >>= 1) m = fmaxf(m, __shfl_xor_sync(0xffffffffu, m, o));
        float4 e;
        e.x = __expf(v.x - m); e.y = __expf(v.y - m);
        e.z = __expf(v.z - m); e.w = __expf(v.w - m);
        float s = e.x + e.y + e.z + e.w;
        #pragma unroll
        for (int o = 16; o; o >>= 1) s += __shfl_xor_sync(0xffffffffu, s, o);
        float inv = 1.0f / s;
        e.x *= inv; e.y *= inv; e.z *= inv; e.w *= inv;
        ((float4*)(sn + r * KK))[lane] = e;
    }
}

// ---------------- packed f32x2 helpers ----------------
__device__ __forceinline__ unsigned long long dup2(float v) {
    unsigned long long r;
    asm("mov.b64 %0, {%1, %1};" : "=l"(r) : "f"(v));
    return r;
}
__device__ __forceinline__ void ffma2(unsigned long long& d,
                                      unsigned long long a, unsigned long long b) {
    asm("fma.rn.f32x2 %0, %1, %2, %0;" : "+l"(d) : "l"(a), "l"(b));
}

// ---------------- fused level kernel ----------------
// One block = (node, b-tile of NB*8 rows). Stages:
//  (A) [leaf only] cache per-k Gaussian params in smem
//  (B) load softmax-weights tile transposed j-major into smem (WsT[j][u])
//  (C) v = child_a + child_b (or fused leaf densities); rowmax m; Es[b][j]=exp(v-m)
//  (D) GEMM: acc2[b][upair] += dup(e) * WsT-pair, fma.rn.f32x2
//  (E) out = m + logf(acc)
template<int NB, bool LEAF>
__global__ void __launch_bounds__(128) level_kernel(
    int insel, int outsel, int woff,
    const float* __restrict__ x, const float* __restrict__ mu,
    const float* __restrict__ ls, float* __restrict__ dout)
{
    constexpr int BT = NB * 8;
    extern __shared__ float smem[];
    float* WsT  = smem;                    // [128][130] j-major
    float* Es   = smem + 128 * 130;        // [BT][132]
    float* Ms   = Es + BT * 132;           // [BT]
    float* Pmua = Ms + BT;                 // leaf params (5 x 128)
    float* Pisa = Pmua + 128;
    float* Pmub = Pisa + 128;
    float* Pisb = Pmub + 128;
    float* Pc   = Pisb + 128;

    const int node = blockIdx.x;
    const int b0   = blockIdx.y * BT;
    const int tid  = threadIdx.x;
    const int warp = tid >> 5, lane = tid & 31;

    const float* yin = (insel == 0) ? g_buf0 : g_buf1;
    float* yout = (outsel == 0) ? g_buf0 : ((outsel == 1) ? g_buf1 : dout);

    if (LEAF) {
        // per-k Gaussian params for the two child variables
        int va = 2 * node, vb = 2 * node + 1;
        float la = ls[va * KK + tid], lb = ls[vb * KK + tid];
        Pmua[tid] = mu[va * KK + tid];
        Pmub[tid] = mu[vb * KK + tid];
        Pisa[tid] = __expf(-la);
        Pisb[tid] = __expf(-lb);
        Pc[tid]   = -la - lb - 1.8378770664093453f;   // ln(2*pi)
        __syncthreads();
    }

    // (B) weights tile, transposed into j-major rows
    {
        const float* swn = g_sw + (size_t)(woff + node) * (KK * KK);
        for (int i = warp; i < KK; i += 4) {
            float4 w4 = ((const float4*)(swn + i * KK))[lane];
            int j = lane * 4;
            WsT[(j + 0) * 130 + i] = w4.x;
            WsT[(j + 1) * 130 + i] = w4.y;
            WsT[(j + 2) * 130 + i] = w4.z;
            WsT[(j + 3) * 130 + i] = w4.w;
        }
    }

    // (C) product + max + exp
    for (int r = warp; r < BT; r += 4) {
        const int b = b0 + r;
        float4 v;
        if (LEAF) {
            float xa = x[b * DD + 2 * node];
            float xb = x[b * DD + 2 * node + 1];
            int k = lane * 4;
            float4 ma = *(const float4*)&Pmua[k];
            float4 ia = *(const float4*)&Pisa[k];
            float4 mb = *(const float4*)&Pmub[k];
            float4 ib = *(const float4*)&Pisb[k];
            float4 cc = *(const float4*)&Pc[k];
            float t, u;
            t = (xa - ma.x) * ia.x; u = (xb - mb.x) * ib.x; v.x = cc.x - 0.5f * (t * t + u * u);
            t = (xa - ma.y) * ia.y; u = (xb - mb.y) * ib.y; v.y = cc.y - 0.5f * (t * t + u * u);
            t = (xa - ma.z) * ia.z; u = (xb - mb.z) * ib.z; v.z = cc.z - 0.5f * (t * t + u * u);
            t = (xa - ma.w) * ia.w; u = (xb - mb.w) * ib.w; v.w = cc.w - 0.5f * (t * t + u * u);
        } else {
            const float* ya = yin + (size_t)(2 * node) * BK + b * KK;
            float4 a4 = ((const float4*)ya)[lane];
            float4 b4 = ((const float4*)(ya + BK))[lane];
            v.x = a4.x + b4.x; v.y = a4.y + b4.y;
            v.z = a4.z + b4.z; v.w = a4.w + b4.w;
        }
        float m = fmaxf(fmaxf(v.x, v.y), fmaxf(v.z, v.w));
        #pragma unroll
        for (int o = 16; o; o >>= 1) m = fmaxf(m, __shfl_xor_sync(0xffffffffu, m, o));
        float4 e;
        e.x = __expf(v.x - m); e.y = __expf(v.y - m);
        e.z = __expf(v.z - m); e.w = __expf(v.w - m);
        ((float4*)&Es[r * 132])[lane] = e;
        if (lane == 0) Ms[r] = m;
    }
    __syncthreads();

    // (D) GEMM: thread tile = NB b-rows x 8 u (as 4 f32x2 pairs)
    const int tx = tid & 15, ty = tid >> 4;
    unsigned long long acc[NB][4];
    #pragma unroll
    for (int bb = 0; bb < NB; bb++)
        #pragma unroll
        for (int ii = 0; ii < 4; ii++) acc[bb][ii] = 0ull;

    const float* erow = Es + (ty * NB) * 132;
    #pragma unroll 2
    for (int j = 0; j < KK; ++j) {
        unsigned long long wv[4];
        #pragma unroll
        for (int ii = 0; ii < 4; ii++)
            wv[ii] = *(const unsigned long long*)&WsT[j * 130 + 2 * tx + 32 * ii];
        #pragma unroll
        for (int bb = 0; bb < NB; bb++) {
            unsigned long long e2 = dup2(erow[bb * 132 + j]);
            #pragma unroll
            for (int ii = 0; ii < 4; ii++) ffma2(acc[bb][ii], e2, wv[ii]);
        }
    }

    // (E) epilogue: m + log(s)
    #pragma unroll
    for (int bb = 0; bb < NB; bb++) {
        const int b = b0 + ty * NB + bb;
        const float m = Ms[ty * NB + bb];
        float* orow = yout + (size_t)node * BK + b * KK;
        #pragma unroll
        for (int ii = 0; ii < 4; ii++) {
            float lo = __uint_as_float((unsigned)(acc[bb][ii]));
            float hi = __uint_as_float((unsigned)(acc[bb][ii] >> 32));
            float2 o;
            o.x = m + __logf(lo);
            o.y = m + __logf(hi);
            *(float2*)&orow[2 * tx + 32 * ii] = o;
        }
    }
}

extern "C" void kernel_launch(void* const* d_in, const int* in_sizes, int n_in,
                              void* d_out, int out_size) {
    const float* x  = (const float*)d_in[0];
    const float* mu = (const float*)d_in[1];
    const float* ls = (const float*)d_in[2];
    const float* w  = (const float*)d_in[3];
    float* out = (float*)d_out;

    const int smem8 = (128 * 130 + 64 * 132 + 64 + 5 * 128) * 4;   // ~103 KB
    const int smem2 = (128 * 130 + 16 * 132 + 16 + 5 * 128) * 4;   // ~78 KB
    cudaFuncSetAttribute(level_kernel<8, true>,  cudaFuncAttributeMaxDynamicSharedMemorySize, smem8);
    cudaFuncSetAttribute(level_kernel<8, false>, cudaFuncAttributeMaxDynamicSharedMemorySize, smem8);
    cudaFuncSetAttribute(level_kernel<2, false>, cudaFuncAttributeMaxDynamicSharedMemorySize, smem2);

    softmax_kernel<<<NNODES, 256>>>(w);

    // level 0 (d=512): fused leaves -> buf0
    level_kernel<8, true><<<dim3(512, 4), 128, smem8>>>(-1, 0, 0, x, mu, ls, out);

    int off = 512, cur = 0;
    const int ds[9] = {256, 128, 64, 32, 16, 8, 4, 2, 1};
    for (int li = 0; li < 9; li++) {
        int d = ds[li];
        int outsel = (li == 8) ? 2 : (1 - cur);
        if (d >= 32)
            level_kernel<8, false><<<dim3(d, 4), 128, smem8>>>(cur, outsel, off, x, mu, ls, out);
        else
            level_kernel<2, false><<<dim3(d, 16), 128, smem2>>>(cur, outsel, off, x, mu, ls, out);
        off += d;
        cur = 1 - cur;
    }
}

// round 3
// speedup vs baseline: 1.3742x; 1.3742x over previous
#include <cuda_runtime.h>
#include <cuda_fp16.h>
#include <mma.h>
#include <stdint.h>

using namespace nvcuda;

#define KK 128
#define BATCH 256
#define DD 1024
#define BK (BATCH*KK)

// ping-pong intermediates (allocation-free rule: __device__ globals)
__device__ float g_buf0[512 * BATCH * KK];
__device__ float g_buf1[256 * BATCH * KK];

// ---------------- smem layout (bytes) ----------------
// A tile: E fp16 [128 m][136]          [0, 34816)
// B tile: softmax(W) fp16 [128 i][136] [34816, 69632)
// Out f32 [128][132] ALIASED at 0 (A/W dead after mma loop)
// Ms f32[128] at 69632, leaf params 5x128 f32 at 70144
#define SM_A    0
#define SM_W    34816
#define SM_MS   69632
#define SM_P    70144
#define SMEM_BYTES (SM_P + 5*128*4)

#define LDA 136   // fp16 elements
#define LDO 132   // fp32 elements

// ---------------- fused level kernel ----------------
// block = (node, 128-row batch tile), 256 threads / 8 warps
template<bool LEAF>
__global__ void __launch_bounds__(256) level_kernel(
    int insel, int outsel, int woff,
    const float* __restrict__ x, const float* __restrict__ mu,
    const float* __restrict__ ls, const float* __restrict__ w,
    float* __restrict__ dout)
{
    extern __shared__ char smem[];
    __half* As = (__half*)(smem + SM_A);
    __half* Wh = (__half*)(smem + SM_W);
    float* OutS = (float*)(smem + SM_A);      // alias, used after mma loop
    float* Ms   = (float*)(smem + SM_MS);
    float* Pmua = (float*)(smem + SM_P);
    float* Pisa = Pmua + 128;
    float* Pmub = Pisa + 128;
    float* Pisb = Pmub + 128;
    float* Pc   = Pisb + 128;

    const int tid  = threadIdx.x;
    const int wid  = tid >> 5, lane = tid & 31;
    const int node = blockIdx.y;
    const int b0   = blockIdx.x * 128;

    const float* yin = (insel == 0) ? g_buf0 : g_buf1;
    float* yout = (outsel == 0) ? g_buf0 : ((outsel == 1) ? g_buf1 : dout);

    // --- stage 0: leaf params ---
    if (LEAF) {
        if (tid < 128) {
            int va = 2 * node, vb = 2 * node + 1;
            float la = ls[va * KK + tid], lb = ls[vb * KK + tid];
            Pmua[tid] = mu[va * KK + tid];
            Pmub[tid] = mu[vb * KK + tid];
            Pisa[tid] = __expf(-la);
            Pisb[tid] = __expf(-lb);
            Pc[tid]   = -la - lb - 1.8378770664093453f;   // -ln(2*pi)
        }
        __syncthreads();
    }

    // --- stage 1: fused softmax(W) -> fp16 B tile (row i, j contiguous) ---
    {
        const float* wn = w + (size_t)(woff + node) * (KK * KK);
        for (int i = wid; i < KK; i += 8) {
            float4 v = ((const float4*)(wn + i * KK))[lane];
            float m = fmaxf(fmaxf(v.x, v.y), fmaxf(v.z, v.w));
            #pragma unroll
            for (int o = 16; o; o >>= 1) m = fmaxf(m, __shfl_xor_sync(0xffffffffu, m, o));
            float e0 = __expf(v.x - m), e1 = __expf(v.y - m);
            float e2 = __expf(v.z - m), e3 = __expf(v.w - m);
            float s = e0 + e1 + e2 + e3;
            #pragma unroll
            for (int o = 16; o; o >>= 1) s += __shfl_xor_sync(0xffffffffu, s, o);
            float inv = 1.0f / s;
            __half2 h0 = __floats2half2_rn(e0 * inv, e1 * inv);
            __half2 h1 = __floats2half2_rn(e2 * inv, e3 * inv);
            uint2 pk;
            pk.x = *(uint32_t*)&h0; pk.y = *(uint32_t*)&h1;
            *(uint2*)&Wh[i * LDA + 4 * lane] = pk;
        }
    }

    // --- stage 2: v = child-sum (or leaf Gaussians), rowmax, exp -> fp16 A tile ---
    // 2 threads per row: r = tid>>1, half j0 = (tid&1)*64
    {
        const int r = tid >> 1;
        const int j0 = (tid & 1) * 64;
        float vbuf[64];
        float mrow = -3.0e38f;
        if (LEAF) {
            float xa = x[(size_t)(b0 + r) * DD + 2 * node];
            float xb = x[(size_t)(b0 + r) * DD + 2 * node + 1];
            #pragma unroll 4
            for (int c = 0; c < 16; c++) {
                int k = j0 + 4 * c;
                float4 ma = *(const float4*)&Pmua[k];
                float4 ia = *(const float4*)&Pisa[k];
                float4 mb = *(const float4*)&Pmub[k];
                float4 ib = *(const float4*)&Pisb[k];
                float4 cc = *(const float4*)&Pc[k];
                float t, u;
                t = (xa - ma.x) * ia.x; u = (xb - mb.x) * ib.x; vbuf[4*c+0] = cc.x - 0.5f * (t*t + u*u);
                t = (xa - ma.y) * ia.y; u = (xb - mb.y) * ib.y; vbuf[4*c+1] = cc.y - 0.5f * (t*t + u*u);
                t = (xa - ma.z) * ia.z; u = (xb - mb.z) * ib.z; vbuf[4*c+2] = cc.z - 0.5f * (t*t + u*u);
                t = (xa - ma.w) * ia.w; u = (xb - mb.w) * ib.w; vbuf[4*c+3] = cc.w - 0.5f * (t*t + u*u);
                mrow = fmaxf(mrow, fmaxf(fmaxf(vbuf[4*c], vbuf[4*c+1]), fmaxf(vbuf[4*c+2], vbuf[4*c+3])));
            }
        } else {
            const float* ya = yin + ((size_t)(2 * node) * BATCH + b0 + r) * KK + j0;
            #pragma unroll 4
            for (int c = 0; c < 16; c++) {
                float4 a4 = ((const float4*)ya)[c];
                float4 c4 = ((const float4*)(ya + BK))[c];
                vbuf[4*c+0] = a4.x + c4.x; vbuf[4*c+1] = a4.y + c4.y;
                vbuf[4*c+2] = a4.z + c4.z; vbuf[4*c+3] = a4.w + c4.w;
                mrow = fmaxf(mrow, fmaxf(fmaxf(vbuf[4*c], vbuf[4*c+1]), fmaxf(vbuf[4*c+2], vbuf[4*c+3])));
            }
        }
        // pairwise rowmax (partner lane differs in bit 0)
        mrow = fmaxf(mrow, __shfl_xor_sync(0xffffffffu, mrow, 1));
        if ((tid & 1) == 0) Ms[r] = mrow;
        #pragma unroll 8
        for (int c = 0; c < 32; c++) {
            __half2 h = __floats2half2_rn(__expf(vbuf[2*c] - mrow), __expf(vbuf[2*c+1] - mrow));
            *(__half2*)&As[r * LDA + j0 + 2 * c] = h;
        }
    }
    __syncthreads();

    // --- stage 3: WMMA GEMM: Out[m,i] = sum_j As[m,j] * Wh[i,j] ---
    // warp grid 2(m) x 4(n): each warp 64m x 32n
    {
        const int warp_m = wid & 1, warp_n = wid >> 1;
        const int m_base = warp_m * 64, n_base = warp_n * 32;
        wmma::fragment<wmma::accumulator, 16, 16, 16, float> acc[4][2];
        #pragma unroll
        for (int i = 0; i < 4; i++)
            #pragma unroll
            for (int j = 0; j < 2; j++) wmma::fill_fragment(acc[i][j], 0.0f);

        #pragma unroll
        for (int k = 0; k < 8; k++) {
            wmma::fragment<wmma::matrix_a, 16, 16, 16, __half, wmma::row_major> af[4];
            wmma::fragment<wmma::matrix_b, 16, 16, 16, __half, wmma::col_major> bf[2];
            #pragma unroll
            for (int i = 0; i < 4; i++)
                wmma::load_matrix_sync(af[i], &As[(m_base + 16 * i) * LDA + 16 * k], LDA);
            #pragma unroll
            for (int j = 0; j < 2; j++)
                wmma::load_matrix_sync(bf[j], &Wh[(n_base + 16 * j) * LDA + 16 * k], LDA);
            #pragma unroll
            for (int i = 0; i < 4; i++)
                #pragma unroll
                for (int j = 0; j < 2; j++)
                    wmma::mma_sync(acc[i][j], af[i], bf[j], acc[i][j]);
        }
        __syncthreads();   // A/W tiles dead -> safe to alias OutS
        #pragma unroll
        for (int i = 0; i < 4; i++)
            #pragma unroll
            for (int j = 0; j < 2; j++)
                wmma::store_matrix_sync(&OutS[(m_base + 16 * i) * LDO + n_base + 16 * j],
                                        acc[i][j], LDO, wmma::mem_row_major);
    }
    __syncthreads();

    // --- stage 4: epilogue out = m + log(s) ---
    {
        const int r = tid >> 1;
        const int j0 = (tid & 1) * 64;
        const float mrow = Ms[r];
        float* orow = yout + ((size_t)node * BATCH + b0 + r) * KK + j0;
        #pragma unroll 4
        for (int c = 0; c < 16; c++) {
            float4 s = *(const float4*)&OutS[r * LDO + j0 + 4 * c];
            float4 o;
            o.x = mrow + __logf(s.x);
            o.y = mrow + __logf(s.y);
            o.z = mrow + __logf(s.z);
            o.w = mrow + __logf(s.w);
            ((float4*)orow)[c] = o;
        }
    }
}

extern "C" void kernel_launch(void* const* d_in, const int* in_sizes, int n_in,
                              void* d_out, int out_size) {
    const float* x  = (const float*)d_in[0];
    const float* mu = (const float*)d_in[1];
    const float* ls = (const float*)d_in[2];
    const float* w  = (const float*)d_in[3];
    float* out = (float*)d_out;

    cudaFuncSetAttribute(level_kernel<true>,  cudaFuncAttributeMaxDynamicSharedMemorySize, SMEM_BYTES);
    cudaFuncSetAttribute(level_kernel<false>, cudaFuncAttributeMaxDynamicSharedMemorySize, SMEM_BYTES);

    // level 0 (d=512): fused leaves -> buf0
    level_kernel<true><<<dim3(2, 512), 256, SMEM_BYTES>>>(-1, 0, 0, x, mu, ls, w, out);

    int off = 512, cur = 0;
    const int ds[9] = {256, 128, 64, 32, 16, 8, 4, 2, 1};
    for (int li = 0; li < 9; li++) {
        int d = ds[li];
        int outsel = (li == 8) ? 2 : (1 - cur);
        level_kernel<false><<<dim3(2, d), 256, SMEM_BYTES>>>(cur, outsel, off, x, mu, ls, w, out);
        off += d;
        cur = 1 - cur;
    }
}

// round 4
// speedup vs baseline: 2.6197x; 1.9063x over previous
#include <cuda_runtime.h>
#include <cuda_fp16.h>
#include <mma.h>
#include <stdint.h>

using namespace nvcuda;

#define KK 128
#define BATCH 256
#define DD 1024
#define BK (BATCH*KK)
#define LDA 136           // halves per smem row (272 B)
#define LDO 132           // floats per out row

// static scratch (allocation-free rule)
__device__ float  g_buf0[512 * BATCH * KK];
__device__ float  g_buf1[256 * BATCH * KK];
__device__ __half g_wh[1023 * KK * KK];      // softmax(W) fp16

// ---------------- helpers ----------------
static __device__ __forceinline__ uint32_t smem_u32(const void* p) {
    uint32_t a;
    asm("{ .reg .u64 t; cvta.to.shared.u64 t, %1; cvt.u32.u64 %0, t; }" : "=r"(a) : "l"(p));
    return a;
}
static __device__ __forceinline__ void cp_async16(uint32_t dst, const void* src) {
    asm volatile("cp.async.cg.shared.global [%0], [%1], 16;" :: "r"(dst), "l"(src));
}
static __device__ __forceinline__ void cp_commit() {
    asm volatile("cp.async.commit_group;" ::: "memory");
}
template<int N> static __device__ __forceinline__ void cp_wait() {
    asm volatile("cp.async.wait_group %0;" :: "n"(N) : "memory");
}

// ---------------- K0: softmax(W) -> fp16, all nodes ----------------
__global__ void __launch_bounds__(256) softmax_w_kernel(const float* __restrict__ w) {
    const int node = blockIdx.x;
    const int wid = threadIdx.x >> 5, lane = threadIdx.x & 31;
    const float* wn = w + (size_t)node * (KK * KK);
    __half* out = g_wh + (size_t)node * (KK * KK);
    for (int i = wid; i < KK; i += 8) {
        float4 v = ((const float4*)(wn + i * KK))[lane];
        float m = fmaxf(fmaxf(v.x, v.y), fmaxf(v.z, v.w));
        #pragma unroll
        for (int o = 16; o; o >>= 1) m = fmaxf(m, __shfl_xor_sync(0xffffffffu, m, o));
        float e0 = __expf(v.x - m), e1 = __expf(v.y - m);
        float e2 = __expf(v.z - m), e3 = __expf(v.w - m);
        float s = e0 + e1 + e2 + e3;
        #pragma unroll
        for (int o = 16; o; o >>= 1) s += __shfl_xor_sync(0xffffffffu, s, o);
        float inv = 1.0f / s;
        __half2 h0 = __floats2half2_rn(e0 * inv, e1 * inv);
        __half2 h1 = __floats2half2_rn(e2 * inv, e3 * inv);
        uint2 pk; pk.x = *(uint32_t*)&h0; pk.y = *(uint32_t*)&h1;
        *(uint2*)&out[i * KK + 4 * lane] = pk;
    }
}

// ---------------- stage-2 core: warp-per-row child-sum/exp -> A tile ----------------
// row handled by one warp; lane covers cols 4*lane..4*lane+3
template<bool LEAF>
static __device__ __forceinline__ void make_A_row(
    __half* As, float* Ms, int row, int lane, int b0, int node,
    const float* yin, const float* x,
    float4 ma, float4 ia, float4 mb, float4 ib, float4 cc)
{
    float4 v;
    if (LEAF) {
        float xa = x[(size_t)(b0 + row) * DD + 2 * node];
        float xb = x[(size_t)(b0 + row) * DD + 2 * node + 1];
        float t, u;
        t = (xa - ma.x) * ia.x; u = (xb - mb.x) * ib.x; v.x = cc.x - 0.5f * (t*t + u*u);
        t = (xa - ma.y) * ia.y; u = (xb - mb.y) * ib.y; v.y = cc.y - 0.5f * (t*t + u*u);
        t = (xa - ma.z) * ia.z; u = (xb - mb.z) * ib.z; v.z = cc.z - 0.5f * (t*t + u*u);
        t = (xa - ma.w) * ia.w; u = (xb - mb.w) * ib.w; v.w = cc.w - 0.5f * (t*t + u*u);
    } else {
        const float* ya = yin + ((size_t)(2 * node) * BATCH + b0 + row) * KK;
        float4 a4 = ((const float4*)ya)[lane];
        float4 c4 = ((const float4*)(ya + BK))[lane];
        v.x = a4.x + c4.x; v.y = a4.y + c4.y; v.z = a4.z + c4.z; v.w = a4.w + c4.w;
    }
    float m = fmaxf(fmaxf(v.x, v.y), fmaxf(v.z, v.w));
    #pragma unroll
    for (int o = 16; o; o >>= 1) m = fmaxf(m, __shfl_xor_sync(0xffffffffu, m, o));
    __half2 h0 = __floats2half2_rn(__expf(v.x - m), __expf(v.y - m));
    __half2 h1 = __floats2half2_rn(__expf(v.z - m), __expf(v.w - m));
    uint2 pk; pk.x = *(uint32_t*)&h0; pk.y = *(uint32_t*)&h1;
    *(uint2*)&As[row * LDA + 4 * lane] = pk;
    if (lane == 0) Ms[row] = m;
}

// ---------------- big-level kernel: MT rows x 128 units, 256 thr ----------------
template<int MT, bool LEAF>
__global__ void __launch_bounds__(256) level_kernel(
    int insel, int outsel, int woff,
    const float* __restrict__ x, const float* __restrict__ mu,
    const float* __restrict__ ls, float* __restrict__ dout)
{
    extern __shared__ char smem[];
    __half* As = (__half*)smem;                         // [MT][LDA]
    __half* Wh = (__half*)(smem + MT * 272);            // [128][LDA]
    float* OutS = (float*)smem;                         // alias, post-MMA
    float* Ms = (float*)(smem + MT * 272 + 34816);
    float* Pm = Ms + MT;                                // leaf params 5x128

    const int tid = threadIdx.x, wid = tid >> 5, lane = tid & 31;
    const int node = blockIdx.y;
    const int b0 = blockIdx.x * MT;
    const uint32_t sW = smem_u32(Wh);

    const float* yin = (insel == 0) ? g_buf0 : g_buf1;
    float* yout = (outsel == 0) ? g_buf0 : ((outsel == 1) ? g_buf1 : dout);

    // async W fp16 tile load (off critical path)
    {
        const char* wsrc = (const char*)(g_wh + (size_t)(woff + node) * (KK * KK));
        #pragma unroll
        for (int c = tid; c < 2048; c += 256)
            cp_async16(sW + (c >> 4) * 272 + (c & 15) * 16, wsrc + (c >> 4) * 256 + (c & 15) * 16);
        cp_commit();
    }

    float4 ma, ia, mb, ib, cc;
    if (LEAF) {
        if (tid < 128) {
            int va = 2 * node, vb = 2 * node + 1;
            float la = ls[va * KK + tid], lb = ls[vb * KK + tid];
            Pm[tid] = mu[va * KK + tid];
            Pm[128 + tid] = __expf(-la);
            Pm[256 + tid] = mu[vb * KK + tid];
            Pm[384 + tid] = __expf(-lb);
            Pm[512 + tid] = -la - lb - 1.8378770664093453f;
        }
        __syncthreads();
        ma = *(const float4*)&Pm[4 * lane];
        ia = *(const float4*)&Pm[128 + 4 * lane];
        mb = *(const float4*)&Pm[256 + 4 * lane];
        ib = *(const float4*)&Pm[384 + 4 * lane];
        cc = *(const float4*)&Pm[512 + 4 * lane];
    }

    // stage 2: A tile
    #pragma unroll
    for (int it = 0; it < MT / 8; it++)
        make_A_row<LEAF>(As, Ms, it * 8 + wid, lane, b0, node, yin, x, ma, ia, mb, ib, cc);

    cp_wait<0>();
    __syncthreads();

    // stage 3: WMMA  Out[m,i] = sum_j A[m,j] * W[i,j]
    constexpr int WM = MT / 2;   // warp m extent (2 x 4 warp grid)
    constexpr int FM = WM / 16;
    {
        const int warp_m = wid & 1, warp_n = wid >> 1;
        const int m_base = warp_m * WM, n_base = warp_n * 32;
        wmma::fragment<wmma::accumulator, 16, 16, 16, float> acc[FM][2];
        #pragma unroll
        for (int i = 0; i < FM; i++)
            #pragma unroll
            for (int j = 0; j < 2; j++) wmma::fill_fragment(acc[i][j], 0.0f);
        #pragma unroll
        for (int k = 0; k < 8; k++) {
            wmma::fragment<wmma::matrix_a, 16, 16, 16, __half, wmma::row_major> af[FM];
            wmma::fragment<wmma::matrix_b, 16, 16, 16, __half, wmma::col_major> bf[2];
            #pragma unroll
            for (int i = 0; i < FM; i++)
                wmma::load_matrix_sync(af[i], &As[(m_base + 16 * i) * LDA + 16 * k], LDA);
            #pragma unroll
            for (int j = 0; j < 2; j++)
                wmma::load_matrix_sync(bf[j], &Wh[(n_base + 16 * j) * LDA + 16 * k], LDA);
            #pragma unroll
            for (int i = 0; i < FM; i++)
                #pragma unroll
                for (int j = 0; j < 2; j++) wmma::mma_sync(acc[i][j], af[i], bf[j], acc[i][j]);
        }
        __syncthreads();   // A/W dead -> alias OutS
        #pragma unroll
        for (int i = 0; i < FM; i++)
            #pragma unroll
            for (int j = 0; j < 2; j++)
                wmma::store_matrix_sync(&OutS[(m_base + 16 * i) * LDO + n_base + 16 * j],
                                        acc[i][j], LDO, wmma::mem_row_major);
    }
    __syncthreads();

    // stage 4: epilogue
    constexpr int TPR = 256 / MT;          // threads per row
    constexpr int CPT = 128 / TPR;         // cols per thread
    {
        const int r = tid / TPR, c0 = (tid % TPR) * CPT;
        const float mrow = Ms[r];
        float* orow = yout + ((size_t)node * BATCH + b0 + r) * KK + c0;
        #pragma unroll
        for (int c = 0; c < CPT / 4; c++) {
            float4 s = *(const float4*)&OutS[r * LDO + c0 + 4 * c];
            float4 o;
            o.x = mrow + __logf(s.x); o.y = mrow + __logf(s.y);
            o.z = mrow + __logf(s.z); o.w = mrow + __logf(s.w);
            ((float4*)orow)[c] = o;
        }
    }
}

// ---------------- fused tail kernel: levels d=16..1, block = 16 batch rows ----------------
#define TBT 16
#define TSM_W0 0
#define TSM_W1 34816
#define TSM_A  69632
#define TSM_O  73984
#define TSM_MS 82432
#define TSM_BYTES (TSM_MS + 64)

__global__ void __launch_bounds__(256) tail_kernel(float* __restrict__ dout)
{
    extern __shared__ char smem[];
    __half* As = (__half*)(smem + TSM_A);
    float* OutS = (float*)(smem + TSM_O);
    float* Ms = (float*)(smem + TSM_MS);
    const uint32_t sb = smem_u32(smem);

    const int tid = threadIdx.x, wid = tid >> 5, lane = tid & 31;
    const int b0 = blockIdx.x * TBT;

    const int LV[5]   = {16, 8, 4, 2, 1};
    const int INSEL[5] = {0, 1, 0, 1, 0};

    // prefetch first W (flat weight index 992)
    {
        const char* ws = (const char*)(g_wh + (size_t)992 * (KK * KK));
        #pragma unroll
        for (int c = tid; c < 2048; c += 256)
            cp_async16(sb + TSM_W0 + (c >> 4) * 272 + (c & 15) * 16, ws + (c >> 4) * 256 + (c & 15) * 16);
        cp_commit();
    }

    int widx = 992;
    int buf = 0;
    for (int li = 0; li < 5; li++) {
        const int d = LV[li];
        const float* yin = (INSEL[li] == 0) ? g_buf0 : g_buf1;
        float* yout = (li == 4) ? dout : ((INSEL[li] == 0) ? g_buf1 : g_buf0);
        for (int node = 0; node < d; node++, widx++, buf ^= 1) {
            // stage A: child-sum/exp tile (overlaps W[widx] cp.async)
            #pragma unroll
            for (int it = 0; it < TBT / 8; it++)
                make_A_row<false>(As, Ms, it * 8 + wid, lane, b0, node, yin, nullptr,
                                  float4{}, float4{}, float4{}, float4{}, float4{});
            // prefetch next W into other buffer
            if (widx < 1022) {
                const char* ws = (const char*)(g_wh + (size_t)(widx + 1) * (KK * KK));
                uint32_t dst = sb + (buf ? TSM_W0 : TSM_W1);
                #pragma unroll
                for (int c = tid; c < 2048; c += 256)
                    cp_async16(dst + (c >> 4) * 272 + (c & 15) * 16, ws + (c >> 4) * 256 + (c & 15) * 16);
                cp_commit();
                cp_wait<1>();
            } else {
                cp_wait<0>();
            }
            __syncthreads();

            // GEMM: 8 warps, each 16m x 16n strip
            __half* Wh = (__half*)(smem + (buf ? TSM_W1 : TSM_W0));
            {
                wmma::fragment<wmma::accumulator, 16, 16, 16, float> acc;
                wmma::fill_fragment(acc, 0.0f);
                #pragma unroll
                for (int k = 0; k < 8; k++) {
                    wmma::fragment<wmma::matrix_a, 16, 16, 16, __half, wmma::row_major> af;
                    wmma::fragment<wmma::matrix_b, 16, 16, 16, __half, wmma::col_major> bf;
                    wmma::load_matrix_sync(af, &As[16 * k], LDA);
                    wmma::load_matrix_sync(bf, &Wh[(wid * 16) * LDA + 16 * k], LDA);
                    wmma::mma_sync(acc, af, bf, acc);
                }
                __syncthreads();
                wmma::store_matrix_sync(&OutS[wid * 16], acc, LDO, wmma::mem_row_major);
            }
            __syncthreads();

            // epilogue: 16 threads/row, 8 cols each
            {
                const int r = tid >> 4, c0 = (tid & 15) * 8;
                const float mrow = Ms[r];
                float* orow = yout + ((size_t)node * BATCH + b0 + r) * KK + c0;
                #pragma unroll
                for (int c = 0; c < 2; c++) {
                    float4 s = *(const float4*)&OutS[r * LDO + c0 + 4 * c];
                    float4 o;
                    o.x = mrow + __logf(s.x); o.y = mrow + __logf(s.y);
                    o.z = mrow + __logf(s.z); o.w = mrow + __logf(s.w);
                    ((float4*)orow)[c] = o;
                }
            }
            // next iteration's mma-side __syncthreads orders OutS reuse;
            // A overwrite is guarded by the sync after cp_wait.
            __syncthreads();
        }
    }
}

extern "C" void kernel_launch(void* const* d_in, const int* in_sizes, int n_in,
                              void* d_out, int out_size) {
    const float* x  = (const float*)d_in[0];
    const float* mu = (const float*)d_in[1];
    const float* ls = (const float*)d_in[2];
    const float* w  = (const float*)d_in[3];
    float* out = (float*)d_out;

    const int sm128 = 128 * 272 + 34816 + 128 * 4 + 5 * 128 * 4;   // 72704
    const int sm64  = 64 * 272 + 34816 + 64 * 4;                   // 52480
    cudaFuncSetAttribute(level_kernel<128, true>,  cudaFuncAttributeMaxDynamicSharedMemorySize, sm128);
    cudaFuncSetAttribute(level_kernel<128, false>, cudaFuncAttributeMaxDynamicSharedMemorySize, sm128);
    cudaFuncSetAttribute(level_kernel<64, false>,  cudaFuncAttributeMaxDynamicSharedMemorySize, sm64);
    cudaFuncSetAttribute(tail_kernel, cudaFuncAttributeMaxDynamicSharedMemorySize, TSM_BYTES);

    softmax_w_kernel<<<1023, 256>>>(w);

    level_kernel<128, true ><<<dim3(2, 512), 256, sm128>>>(-1, 0, 0,   x, mu, ls, out); // d=512 -> buf0
    level_kernel<128, false><<<dim3(2, 256), 256, sm128>>>( 0, 1, 512, x, mu, ls, out); // d=256
    level_kernel<128, false><<<dim3(2, 128), 256, sm128>>>( 1, 0, 768, x, mu, ls, out); // d=128
    level_kernel<64,  false><<<dim3(4, 64),  256, sm64 >>>( 0, 1, 896, x, mu, ls, out); // d=64
    level_kernel<64,  false><<<dim3(4, 32),  256, sm64 >>>( 1, 0, 960, x, mu, ls, out); // d=32 -> buf0
    tail_kernel<<<BATCH / TBT, 256, TSM_BYTES>>>(out);                                  // d=16..1
}

// round 5
// speedup vs baseline: 3.0380x; 1.1597x over previous
#include <cuda_runtime.h>
#include <cuda_fp16.h>
#include <mma.h>
#include <stdint.h>

using namespace nvcuda;

#define KK 128
#define BATCH 256
#define DD 1024
#define BK (BATCH*KK)
#define LDA 136           // halves per smem row (272 B)
#define LDO 132           // floats per out row

// static scratch (allocation-free rule)
__device__ float  g_buf0[512 * BATCH * KK];
__device__ float  g_buf1[256 * BATCH * KK];
__device__ __half g_wh[1023 * KK * KK];      // softmax(W) fp16

// ---------------- helpers ----------------
static __device__ __forceinline__ uint32_t smem_u32(const void* p) {
    uint32_t a;
    asm("{ .reg .u64 t; cvta.to.shared.u64 t, %1; cvt.u32.u64 %0, t; }" : "=r"(a) : "l"(p));
    return a;
}
static __device__ __forceinline__ void cp_async16(uint32_t dst, const void* src) {
    asm volatile("cp.async.cg.shared.global [%0], [%1], 16;" :: "r"(dst), "l"(src));
}
static __device__ __forceinline__ void cp_commit() {
    asm volatile("cp.async.commit_group;" ::: "memory");
}
template<int N> static __device__ __forceinline__ void cp_wait() {
    asm volatile("cp.async.wait_group %0;" :: "n"(N) : "memory");
}

// ---------------- K0: softmax(W) -> fp16, all nodes ----------------
__global__ void __launch_bounds__(256) softmax_w_kernel(const float* __restrict__ w) {
    const int node = blockIdx.x;
    const int wid = threadIdx.x >> 5, lane = threadIdx.x & 31;
    const float* wn = w + (size_t)node * (KK * KK);
    __half* out = g_wh + (size_t)node * (KK * KK);
    for (int i = wid; i < KK; i += 8) {
        float4 v = ((const float4*)(wn + i * KK))[lane];
        float m = fmaxf(fmaxf(v.x, v.y), fmaxf(v.z, v.w));
        #pragma unroll
        for (int o = 16; o; o >>= 1) m = fmaxf(m, __shfl_xor_sync(0xffffffffu, m, o));
        float e0 = __expf(v.x - m), e1 = __expf(v.y - m);
        float e2 = __expf(v.z - m), e3 = __expf(v.w - m);
        float s = e0 + e1 + e2 + e3;
        #pragma unroll
        for (int o = 16; o; o >>= 1) s += __shfl_xor_sync(0xffffffffu, s, o);
        float inv = 1.0f / s;
        __half2 h0 = __floats2half2_rn(e0 * inv, e1 * inv);
        __half2 h1 = __floats2half2_rn(e2 * inv, e3 * inv);
        uint2 pk; pk.x = *(uint32_t*)&h0; pk.y = *(uint32_t*)&h1;
        *(uint2*)&out[i * KK + 4 * lane] = pk;
    }
}

// ---------------- stage-2 core: warp-per-row child-sum/exp -> A tile ----------------
template<bool LEAF>
static __device__ __forceinline__ void make_A_row(
    __half* As, float* Ms, int row, int lane, int b0, int node,
    const float* yin, const float* x,
    float4 ma, float4 ia, float4 mb, float4 ib, float4 cc)
{
    float4 v;
    if (LEAF) {
        float xa = x[(size_t)(b0 + row) * DD + 2 * node];
        float xb = x[(size_t)(b0 + row) * DD + 2 * node + 1];
        float t, u;
        t = (xa - ma.x) * ia.x; u = (xb - mb.x) * ib.x; v.x = cc.x - 0.5f * (t*t + u*u);
        t = (xa - ma.y) * ia.y; u = (xb - mb.y) * ib.y; v.y = cc.y - 0.5f * (t*t + u*u);
        t = (xa - ma.z) * ia.z; u = (xb - mb.z) * ib.z; v.z = cc.z - 0.5f * (t*t + u*u);
        t = (xa - ma.w) * ia.w; u = (xb - mb.w) * ib.w; v.w = cc.w - 0.5f * (t*t + u*u);
    } else {
        const float* ya = yin + ((size_t)(2 * node) * BATCH + b0 + row) * KK;
        float4 a4 = ((const float4*)ya)[lane];
        float4 c4 = ((const float4*)(ya + BK))[lane];
        v.x = a4.x + c4.x; v.y = a4.y + c4.y; v.z = a4.z + c4.z; v.w = a4.w + c4.w;
    }
    float m = fmaxf(fmaxf(v.x, v.y), fmaxf(v.z, v.w));
    #pragma unroll
    for (int o = 16; o; o >>= 1) m = fmaxf(m, __shfl_xor_sync(0xffffffffu, m, o));
    __half2 h0 = __floats2half2_rn(__expf(v.x - m), __expf(v.y - m));
    __half2 h1 = __floats2half2_rn(__expf(v.z - m), __expf(v.w - m));
    uint2 pk; pk.x = *(uint32_t*)&h0; pk.y = *(uint32_t*)&h1;
    *(uint2*)&As[row * LDA + 4 * lane] = pk;
    if (lane == 0) Ms[row] = m;
}

// ---------------- level kernel: MT=64 rows x 128 units, 256 thr, 3+ blocks/SM ----------------
template<bool LEAF>
__global__ void __launch_bounds__(256, 3) level_kernel(
    int insel, int outsel, int woff,
    const float* __restrict__ x, const float* __restrict__ mu,
    const float* __restrict__ ls, float* __restrict__ dout)
{
    constexpr int MT = 64;
    extern __shared__ char smem[];
    __half* As = (__half*)smem;                       // [64][LDA] = 17408 B
    __half* Wh = (__half*)(smem + MT * 272);          // [128][LDA] = 34816 B
    float* OutS = (float*)smem;                       // alias, post-MMA: 64*132*4 = 33792 B
    float* Ms = (float*)(smem + MT * 272 + 34816);
    float* Pm = Ms + MT;

    const int tid = threadIdx.x, wid = tid >> 5, lane = tid & 31;
    const int node = blockIdx.y;
    const int b0 = blockIdx.x * MT;
    const uint32_t sW = smem_u32(Wh);

    const float* yin = (insel == 0) ? g_buf0 : g_buf1;
    float* yout = (outsel == 0) ? g_buf0 : ((outsel == 1) ? g_buf1 : dout);

    // async W fp16 tile load (off critical path)
    {
        const char* wsrc = (const char*)(g_wh + (size_t)(woff + node) * (KK * KK));
        #pragma unroll
        for (int c = tid; c < 2048; c += 256)
            cp_async16(sW + (c >> 4) * 272 + (c & 15) * 16, wsrc + (c >> 4) * 256 + (c & 15) * 16);
        cp_commit();
    }

    float4 ma, ia, mb, ib, cc;
    if (LEAF) {
        if (tid < 128) {
            int va = 2 * node, vb = 2 * node + 1;
            float la = ls[va * KK + tid], lb = ls[vb * KK + tid];
            Pm[tid] = mu[va * KK + tid];
            Pm[128 + tid] = __expf(-la);
            Pm[256 + tid] = mu[vb * KK + tid];
            Pm[384 + tid] = __expf(-lb);
            Pm[512 + tid] = -la - lb - 1.8378770664093453f;
        }
        __syncthreads();
        ma = *(const float4*)&Pm[4 * lane];
        ia = *(const float4*)&Pm[128 + 4 * lane];
        mb = *(const float4*)&Pm[256 + 4 * lane];
        ib = *(const float4*)&Pm[384 + 4 * lane];
        cc = *(const float4*)&Pm[512 + 4 * lane];
    }

    // stage 2: A tile (8 rows per warp)
    #pragma unroll
    for (int it = 0; it < MT / 8; it++)
        make_A_row<LEAF>(As, Ms, it * 8 + wid, lane, b0, node, yin, x, ma, ia, mb, ib, cc);

    cp_wait<0>();
    __syncthreads();

    // stage 3: WMMA  Out[m,i] = sum_j A[m,j] * W[i,j]
    // warp grid 4(m) x 2(n): each warp 16m x 64n (FN=4 accumulators)
    {
        const int warp_m = wid & 3, warp_n = wid >> 2;
        const int m_base = warp_m * 16, n_base = warp_n * 64;
        wmma::fragment<wmma::accumulator, 16, 16, 16, float> acc[4];
        #pragma unroll
        for (int j = 0; j < 4; j++) wmma::fill_fragment(acc[j], 0.0f);
        #pragma unroll
        for (int k = 0; k < 8; k++) {
            wmma::fragment<wmma::matrix_a, 16, 16, 16, __half, wmma::row_major> af;
            wmma::load_matrix_sync(af, &As[m_base * LDA + 16 * k], LDA);
            #pragma unroll
            for (int j = 0; j < 4; j++) {
                wmma::fragment<wmma::matrix_b, 16, 16, 16, __half, wmma::col_major> bf;
                wmma::load_matrix_sync(bf, &Wh[(n_base + 16 * j) * LDA + 16 * k], LDA);
                wmma::mma_sync(acc[j], af, bf, acc[j]);
            }
        }
        __syncthreads();   // A/W dead -> alias OutS
        #pragma unroll
        for (int j = 0; j < 4; j++)
            wmma::store_matrix_sync(&OutS[m_base * LDO + n_base + 16 * j],
                                    acc[j], LDO, wmma::mem_row_major);
    }
    __syncthreads();

    // stage 4: epilogue (4 threads/row, 32 cols each)
    {
        const int r = tid >> 2, c0 = (tid & 3) * 32;
        const float mrow = Ms[r];
        float* orow = yout + ((size_t)node * BATCH + b0 + r) * KK + c0;
        #pragma unroll
        for (int c = 0; c < 8; c++) {
            float4 s = *(const float4*)&OutS[r * LDO + c0 + 4 * c];
            float4 o;
            o.x = mrow + __logf(s.x); o.y = mrow + __logf(s.y);
            o.z = mrow + __logf(s.z); o.w = mrow + __logf(s.w);
            ((float4*)orow)[c] = o;
        }
    }
}

// ---------------- fused tail kernel: levels d=4,2,1; block = 8 batch rows ----------------
#define TBT 8
#define TSM_W0 0
#define TSM_W1 34816
#define TSM_A  69632
#define TSM_O  74240
#define TSM_MS 82688
#define TSM_BYTES (TSM_MS + 64)

__global__ void __launch_bounds__(256) tail_kernel(float* __restrict__ dout)
{
    extern __shared__ char smem[];
    __half* As = (__half*)(smem + TSM_A);      // [16][LDA], rows 8..15 zero
    float* OutS = (float*)(smem + TSM_O);      // [16][LDO]
    float* Ms = (float*)(smem + TSM_MS);
    const uint32_t sb = smem_u32(smem);

    const int tid = threadIdx.x, wid = tid >> 5, lane = tid & 31;
    const int b0 = blockIdx.x * TBT;

    // zero A rows 8..15 once (never rewritten)
    for (int i = tid; i < 8 * 68; i += 256) {
        int rr = 8 + i / 68, cc2 = (i % 68) * 2;
        *(uint32_t*)&As[rr * LDA + cc2] = 0u;
    }

    // prefetch first W (flat weight index 1016)
    {
        const char* ws = (const char*)(g_wh + (size_t)1016 * (KK * KK));
        #pragma unroll
        for (int c = tid; c < 2048; c += 256)
            cp_async16(sb + TSM_W0 + (c >> 4) * 272 + (c & 15) * 16, ws + (c >> 4) * 256 + (c & 15) * 16);
        cp_commit();
    }

    const int LV[3]    = {4, 2, 1};
    const int INSEL[3] = {0, 1, 0};

    int widx = 1016;
    int buf = 0;
    for (int li = 0; li < 3; li++) {
        const int d = LV[li];
        const float* yin = (INSEL[li] == 0) ? g_buf0 : g_buf1;
        float* yout = (li == 2) ? dout : ((INSEL[li] == 0) ? g_buf1 : g_buf0);
        for (int node = 0; node < d; node++, widx++, buf ^= 1) {
            // stage A: warps 0..7 each build one row (rows 0..7)
            make_A_row<false>(As, Ms, wid, lane, b0, node, yin, nullptr,
                              float4{}, float4{}, float4{}, float4{}, float4{});
            // prefetch next W into other buffer
            if (widx < 1022) {
                const char* ws = (const char*)(g_wh + (size_t)(widx + 1) * (KK * KK));
                uint32_t dst = sb + (buf ? TSM_W0 : TSM_W1);
                #pragma unroll
                for (int c = tid; c < 2048; c += 256)
                    cp_async16(dst + (c >> 4) * 272 + (c & 15) * 16, ws + (c >> 4) * 256 + (c & 15) * 16);
                cp_commit();
                cp_wait<1>();
            } else {
                cp_wait<0>();
            }
            __syncthreads();

            // GEMM: 8 warps, each 16m(8 valid) x 16n strip
            __half* Wh = (__half*)(smem + (buf ? TSM_W1 : TSM_W0));
            {
                wmma::fragment<wmma::accumulator, 16, 16, 16, float> acc;
                wmma::fill_fragment(acc, 0.0f);
                #pragma unroll
                for (int k = 0; k < 8; k++) {
                    wmma::fragment<wmma::matrix_a, 16, 16, 16, __half, wmma::row_major> af;
                    wmma::fragment<wmma::matrix_b, 16, 16, 16, __half, wmma::col_major> bf;
                    wmma::load_matrix_sync(af, &As[16 * k], LDA);
                    wmma::load_matrix_sync(bf, &Wh[(wid * 16) * LDA + 16 * k], LDA);
                    wmma::mma_sync(acc, af, bf, acc);
                }
                wmma::store_matrix_sync(&OutS[wid * 16], acc, LDO, wmma::mem_row_major);
            }
            __syncthreads();

            // epilogue: warp per row (8 rows), 4 cols/lane
            {
                const int r = wid, c0 = lane * 4;
                const float mrow = Ms[r];
                float4 s = *(const float4*)&OutS[r * LDO + c0];
                float4 o;
                o.x = mrow + __logf(s.x); o.y = mrow + __logf(s.y);
                o.z = mrow + __logf(s.z); o.w = mrow + __logf(s.w);
                *(float4*)&dout[0] = o;  // placeholder overwritten below
            }
            // NOTE: the placeholder above is wrong-by-construction; do the real store:
            {
                const int r = wid, c0 = lane * 4;
                const float mrow = Ms[r];
                float* orow = yout + ((size_t)node * BATCH + b0 + r) * KK + c0;
                float4 s = *(const float4*)&OutS[r * LDO + c0];
                float4 o;
                o.x = mrow + __logf(s.x); o.y = mrow + __logf(s.y);
                o.z = mrow + __logf(s.z); o.w = mrow + __logf(s.w);
                *(float4*)orow = o;
            }
            __syncthreads();
        }
    }
}

extern "C" void kernel_launch(void* const* d_in, const int* in_sizes, int n_in,
                              void* d_out, int out_size) {
    const float* x  = (const float*)d_in[0];
    const float* mu = (const float*)d_in[1];
    const float* ls = (const float*)d_in[2];
    const float* w  = (const float*)d_in[3];
    float* out = (float*)d_out;

    const int smL = 64 * 272 + 34816 + 64 * 4 + 5 * 128 * 4;   // 55040 (leaf)
    const int smN = 64 * 272 + 34816 + 64 * 4;                 // 52480
    cudaFuncSetAttribute(level_kernel<true>,  cudaFuncAttributeMaxDynamicSharedMemorySize, smL);
    cudaFuncSetAttribute(level_kernel<false>, cudaFuncAttributeMaxDynamicSharedMemorySize, smN);
    cudaFuncSetAttribute(tail_kernel, cudaFuncAttributeMaxDynamicSharedMemorySize, TSM_BYTES);

    softmax_w_kernel<<<1023, 256>>>(w);

    level_kernel<true ><<<dim3(4, 512), 256, smL>>>(-1, 0, 0,    x, mu, ls, out); // d=512 -> buf0
    level_kernel<false><<<dim3(4, 256), 256, smN>>>( 0, 1, 512,  x, mu, ls, out); // d=256 -> buf1
    level_kernel<false><<<dim3(4, 128), 256, smN>>>( 1, 0, 768,  x, mu, ls, out); // d=128 -> buf0
    level_kernel<false><<<dim3(4, 64),  256, smN>>>( 0, 1, 896,  x, mu, ls, out); // d=64  -> buf1
    level_kernel<false><<<dim3(4, 32),  256, smN>>>( 1, 0, 960,  x, mu, ls, out); // d=32  -> buf0
    level_kernel<false><<<dim3(4, 16),  256, smN>>>( 0, 1, 992,  x, mu, ls, out); // d=16  -> buf1
    level_kernel<false><<<dim3(4, 8),   256, smN>>>( 1, 0, 1008, x, mu, ls, out); // d=8   -> buf0
    tail_kernel<<<BATCH / TBT, 256, TSM_BYTES>>>(out);                            // d=4,2,1
}

// round 6
// speedup vs baseline: 3.7065x; 1.2200x over previous
#include <cuda_runtime.h>
#include <cuda_fp16.h>
#include <mma.h>
#include <stdint.h>

using namespace nvcuda;

#define KK 128
#define BATCH 256
#define DD 1024
#define BK (BATCH*KK)
#define LDA 136           // halves per A/W smem row (272 B)
#define LDS 132           // floats per S smem row

// static scratch (allocation-free rule)
__device__ float  g_buf0[512 * BATCH * KK];
__device__ float  g_buf1[256 * BATCH * KK];
__device__ __half g_wh[1023 * KK * KK];      // softmax(W) fp16

// ---- smem layout (bytes) ----
#define SM_W0   0          // [128][136] fp16 = 34816
#define SM_W1   34816
#define SM_A    69632      // [32][136] fp16 = 8704
#define SM_S0   78336      // [32][132] f32 = 16896
#define SM_S1   95232      // [32][132] f32 = 16896 (leaf params alias head)
#define SM_MSUM 112128     // [32] f32
#define SMEM_BYTES (SM_MSUM + 128)

// ---------------- helpers ----------------
static __device__ __forceinline__ uint32_t smem_u32(const void* p) {
    uint32_t a;
    asm("{ .reg .u64 t; cvta.to.shared.u64 t, %1; cvt.u32.u64 %0, t; }" : "=r"(a) : "l"(p));
    return a;
}
static __device__ __forceinline__ void cp_async16(uint32_t dst, const void* src) {
    asm volatile("cp.async.cg.shared.global [%0], [%1], 16;" :: "r"(dst), "l"(src));
}
static __device__ __forceinline__ void cp_commit() {
    asm volatile("cp.async.commit_group;" ::: "memory");
}
template<int N> static __device__ __forceinline__ void cp_wait() {
    asm volatile("cp.async.wait_group %0;" :: "n"(N) : "memory");
}
static __device__ __forceinline__ float warp_max(float m) {
    #pragma unroll
    for (int o = 16; o; o >>= 1) m = fmaxf(m, __shfl_xor_sync(0xffffffffu, m, o));
    return m;
}
static __device__ __forceinline__ float max4(float4 v) {
    return fmaxf(fmaxf(v.x, v.y), fmaxf(v.z, v.w));
}

// ---------------- K0: softmax(W) -> fp16, all nodes ----------------
__global__ void __launch_bounds__(256) softmax_w_kernel(const float* __restrict__ w) {
    const int node = blockIdx.x;
    const int wid = threadIdx.x >> 5, lane = threadIdx.x & 31;
    const float* wn = w + (size_t)node * (KK * KK);
    __half* out = g_wh + (size_t)node * (KK * KK);
    for (int i = wid; i < KK; i += 8) {
        float4 v = ((const float4*)(wn + i * KK))[lane];
        float m = warp_max(max4(v));
        float e0 = __expf(v.x - m), e1 = __expf(v.y - m);
        float e2 = __expf(v.z - m), e3 = __expf(v.w - m);
        float s = e0 + e1 + e2 + e3;
        #pragma unroll
        for (int o = 16; o; o >>= 1) s += __shfl_xor_sync(0xffffffffu, s, o);
        float inv = 1.0f / s;
        __half2 h0 = __floats2half2_rn(e0 * inv, e1 * inv);
        __half2 h1 = __floats2half2_rn(e2 * inv, e3 * inv);
        uint2 pk; pk.x = *(uint32_t*)&h0; pk.y = *(uint32_t*)&h1;
        *(uint2*)&out[i * KK + 4 * lane] = pk;
    }
}

// ---------------- in-kernel 32x128x128 GEMM: Out[m,i] = sum_j A[m,j]*W[i,j] ----------------
static __device__ __forceinline__ void gemm32(const __half* As, const __half* Wh,
                                              float* Out, int wid) {
    const int warp_m = wid & 1, warp_n = wid >> 1;
    const int m_base = warp_m * 16, n_base = warp_n * 32;
    wmma::fragment<wmma::accumulator, 16, 16, 16, float> acc[2];
    wmma::fill_fragment(acc[0], 0.0f);
    wmma::fill_fragment(acc[1], 0.0f);
    #pragma unroll
    for (int k = 0; k < 8; k++) {
        wmma::fragment<wmma::matrix_a, 16, 16, 16, __half, wmma::row_major> af;
        wmma::load_matrix_sync(af, &As[m_base * LDA + 16 * k], LDA);
        #pragma unroll
        for (int j = 0; j < 2; j++) {
            wmma::fragment<wmma::matrix_b, 16, 16, 16, __half, wmma::col_major> bf;
            wmma::load_matrix_sync(bf, &Wh[(n_base + 16 * j) * LDA + 16 * k], LDA);
            wmma::mma_sync(acc[j], af, bf, acc[j]);
        }
    }
    #pragma unroll
    for (int j = 0; j < 2; j++)
        wmma::store_matrix_sync(&Out[m_base * LDS + n_base + 16 * j], acc[j], LDS,
                                wmma::mem_row_major);
}

static __device__ __forceinline__ void cp_wtile(uint32_t dst, const __half* wsrc, int tid) {
    const char* ws = (const char*)wsrc;
    #pragma unroll
    for (int c = tid; c < 2048; c += 256)
        cp_async16(dst + (c >> 4) * 272 + (c & 15) * 16, ws + (c >> 4) * 256 + (c & 15) * 16);
    cp_commit();
}

// ---------------- fused level-pair kernel ----------------
// Output node n (upper level) from lower-level children c0=2n, c1=2n+1, whose
// inputs are grandchildren 4n..4n+3 (or leaf Gaussians of vars 4n..4n+3).
// Pipeline: build A0 (+hold v1/m1 in regs) | GEMM1 -> S0 | A1 from regs |
//           GEMM2 -> S1 | E' = S0*S1/rowmax, m' = m0+m1+log(rowmax) | GEMM3 -> S0 |
//           out = m' + log(S0).
template<bool LEAF>
__global__ void __launch_bounds__(256, 2) pair_kernel(
    int insel, int outsel, int wlo, int wup,
    const float* __restrict__ x, const float* __restrict__ mu,
    const float* __restrict__ ls, float* __restrict__ dout)
{
    extern __shared__ char smem[];
    __half* As = (__half*)(smem + SM_A);
    float* S0  = (float*)(smem + SM_S0);
    float* S1  = (float*)(smem + SM_S1);
    float* Pm  = (float*)(smem + SM_S1);     // leaf params alias S1 head (consumed pre-GEMM2)
    float* Msum = (float*)(smem + SM_MSUM);
    const uint32_t sb = smem_u32(smem);

    const int tid = threadIdx.x, wid = tid >> 5, lane = tid & 31;
    const int node = blockIdx.y;
    const int b0 = blockIdx.x * 32;

    const float* yin = (insel == 0) ? g_buf0 : g_buf1;
    float* yout = (outsel == 0) ? g_buf0 : ((outsel == 1) ? g_buf1 : dout);

    // prefetch W_c0, W_c1
    cp_wtile(sb + SM_W0, g_wh + (size_t)(wlo + 2 * node) * (KK * KK), tid);
    cp_wtile(sb + SM_W1, g_wh + (size_t)(wlo + 2 * node + 1) * (KK * KK), tid);

    if (LEAF) {
        if (tid < 128) {
            int v0 = 4 * node, v1 = 4 * node + 1, v2 = 4 * node + 2, v3 = 4 * node + 3;
            float l0 = ls[v0 * KK + tid], l1 = ls[v1 * KK + tid];
            float l2 = ls[v2 * KK + tid], l3 = ls[v3 * KK + tid];
            Pm[0 * 128 + tid] = mu[v0 * KK + tid];
            Pm[1 * 128 + tid] = __expf(-l0);
            Pm[2 * 128 + tid] = mu[v1 * KK + tid];
            Pm[3 * 128 + tid] = __expf(-l1);
            Pm[4 * 128 + tid] = -l0 - l1 - 1.8378770664093453f;
            Pm[5 * 128 + tid] = mu[v2 * KK + tid];
            Pm[6 * 128 + tid] = __expf(-l2);
            Pm[7 * 128 + tid] = mu[v3 * KK + tid];
            Pm[8 * 128 + tid] = __expf(-l3);
            Pm[9 * 128 + tid] = -l2 - l3 - 1.8378770664093453f;
        }
        __syncthreads();
    }

    // ---- merged build: A0 tile to smem; v1/m0/m1 held in registers ----
    float4 v1r[4];
    float m0r[4], m1r[4];
    #pragma unroll
    for (int it = 0; it < 4; it++) {
        const int r = it * 8 + wid;
        float4 v0, v1;
        if (LEAF) {
            float4 xq = *(const float4*)&x[(size_t)(b0 + r) * DD + 4 * node];
            float4 ma0 = *(const float4*)&Pm[0 * 128 + 4 * lane];
            float4 ia0 = *(const float4*)&Pm[1 * 128 + 4 * lane];
            float4 mb0 = *(const float4*)&Pm[2 * 128 + 4 * lane];
            float4 ib0 = *(const float4*)&Pm[3 * 128 + 4 * lane];
            float4 cc0 = *(const float4*)&Pm[4 * 128 + 4 * lane];
            float4 ma1 = *(const float4*)&Pm[5 * 128 + 4 * lane];
            float4 ia1 = *(const float4*)&Pm[6 * 128 + 4 * lane];
            float4 mb1 = *(const float4*)&Pm[7 * 128 + 4 * lane];
            float4 ib1 = *(const float4*)&Pm[8 * 128 + 4 * lane];
            float4 cc1 = *(const float4*)&Pm[9 * 128 + 4 * lane];
            float t, u;
            t = (xq.x - ma0.x) * ia0.x; u = (xq.y - mb0.x) * ib0.x; v0.x = cc0.x - 0.5f * (t*t + u*u);
            t = (xq.x - ma0.y) * ia0.y; u = (xq.y - mb0.y) * ib0.y; v0.y = cc0.y - 0.5f * (t*t + u*u);
            t = (xq.x - ma0.z) * ia0.z; u = (xq.y - mb0.z) * ib0.z; v0.z = cc0.z - 0.5f * (t*t + u*u);
            t = (xq.x - ma0.w) * ia0.w; u = (xq.y - mb0.w) * ib0.w; v0.w = cc0.w - 0.5f * (t*t + u*u);
            t = (xq.z - ma1.x) * ia1.x; u = (xq.w - mb1.x) * ib1.x; v1.x = cc1.x - 0.5f * (t*t + u*u);
            t = (xq.z - ma1.y) * ia1.y; u = (xq.w - mb1.y) * ib1.y; v1.y = cc1.y - 0.5f * (t*t + u*u);
            t = (xq.z - ma1.z) * ia1.z; u = (xq.w - mb1.z) * ib1.z; v1.z = cc1.z - 0.5f * (t*t + u*u);
            t = (xq.z - ma1.w) * ia1.w; u = (xq.w - mb1.w) * ib1.w; v1.w = cc1.w - 0.5f * (t*t + u*u);
        } else {
            const float* yg = yin + ((size_t)(4 * node) * BATCH + b0 + r) * KK;
            float4 a = ((const float4*)yg)[lane];
            float4 b = ((const float4*)(yg + BK))[lane];
            float4 c = ((const float4*)(yg + 2 * BK))[lane];
            float4 d = ((const float4*)(yg + 3 * BK))[lane];
            v0.x = a.x + b.x; v0.y = a.y + b.y; v0.z = a.z + b.z; v0.w = a.w + b.w;
            v1.x = c.x + d.x; v1.y = c.y + d.y; v1.z = c.z + d.z; v1.w = c.w + d.w;
        }
        float m0 = warp_max(max4(v0));
        float m1 = warp_max(max4(v1));
        __half2 h0 = __floats2half2_rn(__expf(v0.x - m0), __expf(v0.y - m0));
        __half2 h1 = __floats2half2_rn(__expf(v0.z - m0), __expf(v0.w - m0));
        uint2 pk; pk.x = *(uint32_t*)&h0; pk.y = *(uint32_t*)&h1;
        *(uint2*)&As[r * LDA + 4 * lane] = pk;
        v1r[it] = v1; m0r[it] = m0; m1r[it] = m1;
    }

    cp_wait<1>();            // W_c0 ready
    __syncthreads();
    gemm32(As, (const __half*)(smem + SM_W0), S0, wid);
    __syncthreads();

    // prefetch W_n into buf0 (GEMM1 done with it)
    cp_wtile(sb + SM_W0, g_wh + (size_t)(wup + node) * (KK * KK), tid);

    // A1 from registers
    #pragma unroll
    for (int it = 0; it < 4; it++) {
        const int r = it * 8 + wid;
        float4 v1 = v1r[it];
        float m1 = m1r[it];
        __half2 h0 = __floats2half2_rn(__expf(v1.x - m1), __expf(v1.y - m1));
        __half2 h1 = __floats2half2_rn(__expf(v1.z - m1), __expf(v1.w - m1));
        uint2 pk; pk.x = *(uint32_t*)&h0; pk.y = *(uint32_t*)&h1;
        *(uint2*)&As[r * LDA + 4 * lane] = pk;
    }

    cp_wait<1>();            // W_c1 ready
    __syncthreads();
    gemm32(As, (const __half*)(smem + SM_W1), S1, wid);
    __syncthreads();

    // ---- product + renorm: E' = S0*S1/rowmax, m' = m0+m1+log(rowmax) ----
    #pragma unroll
    for (int it = 0; it < 4; it++) {
        const int r = it * 8 + wid;
        float4 s0 = *(const float4*)&S0[r * LDS + 4 * lane];
        float4 s1 = *(const float4*)&S1[r * LDS + 4 * lane];
        float4 p;
        p.x = s0.x * s1.x; p.y = s0.y * s1.y; p.z = s0.z * s1.z; p.w = s0.w * s1.w;
        float pmax = fmaxf(warp_max(max4(p)), 1e-35f);
        float inv = __fdividef(1.0f, pmax);
        __half2 h0 = __floats2half2_rn(p.x * inv, p.y * inv);
        __half2 h1 = __floats2half2_rn(p.z * inv, p.w * inv);
        uint2 pk; pk.x = *(uint32_t*)&h0; pk.y = *(uint32_t*)&h1;
        *(uint2*)&As[r * LDA + 4 * lane] = pk;
        if (lane == 0) Msum[r] = m0r[it] + m1r[it] + __logf(pmax);
    }

    cp_wait<0>();            // W_n ready
    __syncthreads();
    gemm32(As, (const __half*)(smem + SM_W0), S0, wid);
    __syncthreads();

    // ---- epilogue: out = m' + log(s) ----
    {
        const int r = tid >> 3, c0 = (tid & 7) * 16;
        const float mrow = Msum[r];
        float* orow = yout + ((size_t)node * BATCH + b0 + r) * KK + c0;
        #pragma unroll
        for (int c = 0; c < 4; c++) {
            float4 s = *(const float4*)&S0[r * LDS + c0 + 4 * c];
            float4 o;
            o.x = mrow + __logf(s.x); o.y = mrow + __logf(s.y);
            o.z = mrow + __logf(s.z); o.w = mrow + __logf(s.w);
            ((float4*)orow)[c] = o;
        }
    }
}

extern "C" void kernel_launch(void* const* d_in, const int* in_sizes, int n_in,
                              void* d_out, int out_size) {
    const float* x  = (const float*)d_in[0];
    const float* mu = (const float*)d_in[1];
    const float* ls = (const float*)d_in[2];
    const float* w  = (const float*)d_in[3];
    float* out = (float*)d_out;

    cudaFuncSetAttribute(pair_kernel<true>,  cudaFuncAttributeMaxDynamicSharedMemorySize, SMEM_BYTES);
    cudaFuncSetAttribute(pair_kernel<false>, cudaFuncAttributeMaxDynamicSharedMemorySize, SMEM_BYTES);

    softmax_w_kernel<<<1023, 256>>>(w);

    // pairs: (leaf512+256) (128+64) (32+16) (8+4) (2+1)
    pair_kernel<true ><<<dim3(8, 256), 256, SMEM_BYTES>>>(-1, 0, 0,    512,  x, mu, ls, out); // -> buf0 (256 nodes)
    pair_kernel<false><<<dim3(8, 64),  256, SMEM_BYTES>>>( 0, 1, 768,  896,  x, mu, ls, out); // -> buf1 (64)
    pair_kernel<false><<<dim3(8, 16),  256, SMEM_BYTES>>>( 1, 0, 960,  992,  x, mu, ls, out); // -> buf0 (16)
    pair_kernel<false><<<dim3(8, 4),   256, SMEM_BYTES>>>( 0, 1, 1008, 1016, x, mu, ls, out); // -> buf1 (4)
    pair_kernel<false><<<dim3(8, 1),   256, SMEM_BYTES>>>( 1, 2, 1020, 1022, x, mu, ls, out); // -> dout (root)
}

// round 7
// speedup vs baseline: 3.8662x; 1.0431x over previous
#include <cuda_runtime.h>
#include <cuda_fp16.h>
#include <mma.h>
#include <stdint.h>

using namespace nvcuda;

#define KK 128
#define BATCH 256
#define DD 1024
#define BK (BATCH*KK)
#define LDA 136           // halves per A/W smem row (272 B)
#define LDS 132           // floats per S smem row

// static scratch (allocation-free rule)
__device__ float  g_buf0[512 * BATCH * KK];
__device__ float  g_buf1[256 * BATCH * KK];
__device__ __half g_wh[1023 * KK * KK];      // softmax(W) fp16

// ---- smem layout (bytes) ----
#define SM_W0   0          // [128][136] fp16 = 34816
#define SM_W1   34816
#define SM_A    69632      // [32][136] fp16 = 8704
#define SM_S0   78336      // [32][132] f32 = 16896 (leaf params alias head)
#define SM_MSUM 95232      // [32] f32
#define SMEM_BYTES (SM_MSUM + 192)   // ~95.4 KB -> 2 blocks/SM

// ---------------- helpers ----------------
static __device__ __forceinline__ uint32_t smem_u32(const void* p) {
    uint32_t a;
    asm("{ .reg .u64 t; cvta.to.shared.u64 t, %1; cvt.u32.u64 %0, t; }" : "=r"(a) : "l"(p));
    return a;
}
static __device__ __forceinline__ void cp_async16(uint32_t dst, const void* src) {
    asm volatile("cp.async.cg.shared.global [%0], [%1], 16;" :: "r"(dst), "l"(src));
}
static __device__ __forceinline__ void cp_commit() {
    asm volatile("cp.async.commit_group;" ::: "memory");
}
template<int N> static __device__ __forceinline__ void cp_wait() {
    asm volatile("cp.async.wait_group %0;" :: "n"(N) : "memory");
}
static __device__ __forceinline__ float warp_max(float m) {
    #pragma unroll
    for (int o = 16; o; o >>= 1) m = fmaxf(m, __shfl_xor_sync(0xffffffffu, m, o));
    return m;
}
static __device__ __forceinline__ float max4(float4 v) {
    return fmaxf(fmaxf(v.x, v.y), fmaxf(v.z, v.w));
}

// ---------------- K0: softmax(W) -> fp16, all nodes ----------------
__global__ void __launch_bounds__(256) softmax_w_kernel(const float* __restrict__ w) {
    const int node = blockIdx.x;
    const int wid = threadIdx.x >> 5, lane = threadIdx.x & 31;
    const float* wn = w + (size_t)node * (KK * KK);
    __half* out = g_wh + (size_t)node * (KK * KK);
    for (int i = wid; i < KK; i += 8) {
        float4 v = ((const float4*)(wn + i * KK))[lane];
        float m = warp_max(max4(v));
        float e0 = __expf(v.x - m), e1 = __expf(v.y - m);
        float e2 = __expf(v.z - m), e3 = __expf(v.w - m);
        float s = e0 + e1 + e2 + e3;
        #pragma unroll
        for (int o = 16; o; o >>= 1) s += __shfl_xor_sync(0xffffffffu, s, o);
        float inv = 1.0f / s;
        __half2 h0 = __floats2half2_rn(e0 * inv, e1 * inv);
        __half2 h1 = __floats2half2_rn(e2 * inv, e3 * inv);
        uint2 pk; pk.x = *(uint32_t*)&h0; pk.y = *(uint32_t*)&h1;
        *(uint2*)&out[i * KK + 4 * lane] = pk;
    }
}

// in-register 32x128x128 GEMM: acc[m,i] = sum_j A[m,j]*W[i,j]; warp tile 16m x 32n
using AccFrag = wmma::fragment<wmma::accumulator, 16, 16, 16, float>;
static __device__ __forceinline__ void gemm32_acc(const __half* As, const __half* Wh,
                                                  AccFrag acc[2], int wid) {
    const int warp_m = wid & 1, warp_n = wid >> 1;
    const int m_base = warp_m * 16, n_base = warp_n * 32;
    wmma::fill_fragment(acc[0], 0.0f);
    wmma::fill_fragment(acc[1], 0.0f);
    #pragma unroll
    for (int k = 0; k < 8; k++) {
        wmma::fragment<wmma::matrix_a, 16, 16, 16, __half, wmma::row_major> af;
        wmma::load_matrix_sync(af, &As[m_base * LDA + 16 * k], LDA);
        #pragma unroll
        for (int j = 0; j < 2; j++) {
            wmma::fragment<wmma::matrix_b, 16, 16, 16, __half, wmma::col_major> bf;
            wmma::load_matrix_sync(bf, &Wh[(n_base + 16 * j) * LDA + 16 * k], LDA);
            wmma::mma_sync(acc[j], af, bf, acc[j]);
        }
    }
}
static __device__ __forceinline__ void store_acc(AccFrag acc[2], float* Out, int wid) {
    const int warp_m = wid & 1, warp_n = wid >> 1;
    #pragma unroll
    for (int j = 0; j < 2; j++)
        wmma::store_matrix_sync(&Out[(warp_m * 16) * LDS + warp_n * 32 + 16 * j],
                                acc[j], LDS, wmma::mem_row_major);
}
static __device__ __forceinline__ void cp_wtile(uint32_t dst, const __half* wsrc, int tid) {
    const char* ws = (const char*)wsrc;
    #pragma unroll
    for (int c = tid; c < 2048; c += 256)
        cp_async16(dst + (c >> 4) * 272 + (c & 15) * 16, ws + (c >> 4) * 256 + (c & 15) * 16);
    cp_commit();
}

// ---------------- fused level-pair kernel ----------------
// Upper node n from lower children c0=2n, c1=2n+1, inputs = grandchildren 4n..4n+3
// (or leaf Gaussians of vars 4n..4n+3).
// GEMM1 acc1 (regs) | A1 | GEMM2 acc2; acc2 *= acc1 (fragment space) -> S0 |
// renorm -> As, m' | GEMM3 -> S0 | out = m' + log(S0)
template<bool LEAF>
__global__ void __launch_bounds__(256, 2) pair_kernel(
    int insel, int outsel, int wlo, int wup,
    const float* __restrict__ x, const float* __restrict__ mu,
    const float* __restrict__ ls, float* __restrict__ dout)
{
    extern __shared__ char smem[];
    __half* As = (__half*)(smem + SM_A);
    float* S0  = (float*)(smem + SM_S0);
    float* Pm  = (float*)(smem + SM_S0);     // leaf params alias S0 (dead until product stage)
    float* Msum = (float*)(smem + SM_MSUM);
    const uint32_t sb = smem_u32(smem);

    const int tid = threadIdx.x, wid = tid >> 5, lane = tid & 31;
    const int node = blockIdx.y;
    const int b0 = blockIdx.x * 32;

    const float* yin = (insel == 0) ? g_buf0 : g_buf1;
    float* yout = (outsel == 0) ? g_buf0 : ((outsel == 1) ? g_buf1 : dout);

    // prefetch W_c0 (group A), W_c1 (group B)
    cp_wtile(sb + SM_W0, g_wh + (size_t)(wlo + 2 * node) * (KK * KK), tid);
    cp_wtile(sb + SM_W1, g_wh + (size_t)(wlo + 2 * node + 1) * (KK * KK), tid);

    if (LEAF) {
        if (tid < 128) {
            int v0 = 4 * node, v1 = 4 * node + 1, v2 = 4 * node + 2, v3 = 4 * node + 3;
            float l0 = ls[v0 * KK + tid], l1 = ls[v1 * KK + tid];
            float l2 = ls[v2 * KK + tid], l3 = ls[v3 * KK + tid];
            Pm[0 * 128 + tid] = mu[v0 * KK + tid];
            Pm[1 * 128 + tid] = __expf(-l0);
            Pm[2 * 128 + tid] = mu[v1 * KK + tid];
            Pm[3 * 128 + tid] = __expf(-l1);
            Pm[4 * 128 + tid] = -l0 - l1 - 1.8378770664093453f;
            Pm[5 * 128 + tid] = mu[v2 * KK + tid];
            Pm[6 * 128 + tid] = __expf(-l2);
            Pm[7 * 128 + tid] = mu[v3 * KK + tid];
            Pm[8 * 128 + tid] = __expf(-l3);
            Pm[9 * 128 + tid] = -l2 - l3 - 1.8378770664093453f;
        }
        __syncthreads();
    }

    // ---- merged build: A0 tile to smem; v1/m0/m1 held in registers ----
    float4 v1r[4];
    float m0r[4], m1r[4];
    #pragma unroll
    for (int it = 0; it < 4; it++) {
        const int r = it * 8 + wid;
        float4 v0, v1;
        if (LEAF) {
            float4 xq = *(const float4*)&x[(size_t)(b0 + r) * DD + 4 * node];
            float4 ma0 = *(const float4*)&Pm[0 * 128 + 4 * lane];
            float4 ia0 = *(const float4*)&Pm[1 * 128 + 4 * lane];
            float4 mb0 = *(const float4*)&Pm[2 * 128 + 4 * lane];
            float4 ib0 = *(const float4*)&Pm[3 * 128 + 4 * lane];
            float4 cc0 = *(const float4*)&Pm[4 * 128 + 4 * lane];
            float4 ma1 = *(const float4*)&Pm[5 * 128 + 4 * lane];
            float4 ia1 = *(const float4*)&Pm[6 * 128 + 4 * lane];
            float4 mb1 = *(const float4*)&Pm[7 * 128 + 4 * lane];
            float4 ib1 = *(const float4*)&Pm[8 * 128 + 4 * lane];
            float4 cc1 = *(const float4*)&Pm[9 * 128 + 4 * lane];
            float t, u;
            t = (xq.x - ma0.x) * ia0.x; u = (xq.y - mb0.x) * ib0.x; v0.x = cc0.x - 0.5f * (t*t + u*u);
            t = (xq.x - ma0.y) * ia0.y; u = (xq.y - mb0.y) * ib0.y; v0.y = cc0.y - 0.5f * (t*t + u*u);
            t = (xq.x - ma0.z) * ia0.z; u = (xq.y - mb0.z) * ib0.z; v0.z = cc0.z - 0.5f * (t*t + u*u);
            t = (xq.x - ma0.w) * ia0.w; u = (xq.y - mb0.w) * ib0.w; v0.w = cc0.w - 0.5f * (t*t + u*u);
            t = (xq.z - ma1.x) * ia1.x; u = (xq.w - mb1.x) * ib1.x; v1.x = cc1.x - 0.5f * (t*t + u*u);
            t = (xq.z - ma1.y) * ia1.y; u = (xq.w - mb1.y) * ib1.y; v1.y = cc1.y - 0.5f * (t*t + u*u);
            t = (xq.z - ma1.z) * ia1.z; u = (xq.w - mb1.z) * ib1.z; v1.z = cc1.z - 0.5f * (t*t + u*u);
            t = (xq.z - ma1.w) * ia1.w; u = (xq.w - mb1.w) * ib1.w; v1.w = cc1.w - 0.5f * (t*t + u*u);
        } else {
            const float* yg = yin + ((size_t)(4 * node) * BATCH + b0 + r) * KK;
            float4 a = ((const float4*)yg)[lane];
            float4 b = ((const float4*)(yg + BK))[lane];
            float4 c = ((const float4*)(yg + 2 * BK))[lane];
            float4 d = ((const float4*)(yg + 3 * BK))[lane];
            v0.x = a.x + b.x; v0.y = a.y + b.y; v0.z = a.z + b.z; v0.w = a.w + b.w;
            v1.x = c.x + d.x; v1.y = c.y + d.y; v1.z = c.z + d.z; v1.w = c.w + d.w;
        }
        float m0 = warp_max(max4(v0));
        float m1 = warp_max(max4(v1));
        __half2 h0 = __floats2half2_rn(__expf(v0.x - m0), __expf(v0.y - m0));
        __half2 h1 = __floats2half2_rn(__expf(v0.z - m0), __expf(v0.w - m0));
        uint2 pk; pk.x = *(uint32_t*)&h0; pk.y = *(uint32_t*)&h1;
        *(uint2*)&As[r * LDA + 4 * lane] = pk;
        v1r[it] = v1; m0r[it] = m0; m1r[it] = m1;
    }

    AccFrag acc1[2], acc2[2];

    cp_wait<1>();            // W_c0 ready
    __syncthreads();
    gemm32_acc(As, (const __half*)(smem + SM_W0), acc1, wid);   // acc1 stays in regs
    __syncthreads();         // all warps done reading As and W0

    // prefetch W_up into W0 slot (group C)
    cp_wtile(sb + SM_W0, g_wh + (size_t)(wup + node) * (KK * KK), tid);

    // A1 from registers
    #pragma unroll
    for (int it = 0; it < 4; it++) {
        const int r = it * 8 + wid;
        float4 v1 = v1r[it];
        float m1 = m1r[it];
        __half2 h0 = __floats2half2_rn(__expf(v1.x - m1), __expf(v1.y - m1));
        __half2 h1 = __floats2half2_rn(__expf(v1.z - m1), __expf(v1.w - m1));
        uint2 pk; pk.x = *(uint32_t*)&h0; pk.y = *(uint32_t*)&h1;
        *(uint2*)&As[r * LDA + 4 * lane] = pk;
    }

    cp_wait<1>();            // groups A+B drained -> W_c1 ready
    __syncthreads();
    gemm32_acc(As, (const __half*)(smem + SM_W1), acc2, wid);

    // fragment-space product (identical layouts -> elementwise matrix product)
    #pragma unroll
    for (int j = 0; j < 2; j++)
        #pragma unroll
        for (int e = 0; e < acc2[j].num_elements; e++)
            acc2[j].x[e] *= acc1[j].x[e];
    store_acc(acc2, S0, wid);
    __syncthreads();

    // ---- renorm: E' = P/rowmax -> As, m' = m0+m1+log(rowmax) ----
    #pragma unroll
    for (int it = 0; it < 4; it++) {
        const int r = it * 8 + wid;
        float4 p = *(const float4*)&S0[r * LDS + 4 * lane];
        float pmax = fmaxf(warp_max(max4(p)), 1e-35f);
        float inv = __fdividef(1.0f, pmax);
        __half2 h0 = __floats2half2_rn(p.x * inv, p.y * inv);
        __half2 h1 = __floats2half2_rn(p.z * inv, p.w * inv);
        uint2 pk; pk.x = *(uint32_t*)&h0; pk.y = *(uint32_t*)&h1;
        *(uint2*)&As[r * LDA + 4 * lane] = pk;
        if (lane == 0) Msum[r] = m0r[it] + m1r[it] + __logf(pmax);
    }

    cp_wait<0>();            // W_up ready
    __syncthreads();
    gemm32_acc(As, (const __half*)(smem + SM_W0), acc2, wid);
    store_acc(acc2, S0, wid);
    __syncthreads();

    // ---- epilogue: out = m' + log(s) ----
    {
        const int r = tid >> 3, c0 = (tid & 7) * 16;
        const float mrow = Msum[r];
        float* orow = yout + ((size_t)node * BATCH + b0 + r) * KK + c0;
        #pragma unroll
        for (int c = 0; c < 4; c++) {
            float4 s = *(const float4*)&S0[r * LDS + c0 + 4 * c];
            float4 o;
            o.x = mrow + __logf(s.x); o.y = mrow + __logf(s.y);
            o.z = mrow + __logf(s.z); o.w = mrow + __logf(s.w);
            ((float4*)orow)[c] = o;
        }
    }
}

extern "C" void kernel_launch(void* const* d_in, const int* in_sizes, int n_in,
                              void* d_out, int out_size) {
    const float* x  = (const float*)d_in[0];
    const float* mu = (const float*)d_in[1];
    const float* ls = (const float*)d_in[2];
    const float* w  = (const float*)d_in[3];
    float* out = (float*)d_out;

    cudaFuncSetAttribute(pair_kernel<true>,  cudaFuncAttributeMaxDynamicSharedMemorySize, SMEM_BYTES);
    cudaFuncSetAttribute(pair_kernel<false>, cudaFuncAttributeMaxDynamicSharedMemorySize, SMEM_BYTES);

    softmax_w_kernel<<<1023, 256>>>(w);

    // pairs: (leaf512+256) (128+64) (32+16) (8+4) (2+1)
    pair_kernel<true ><<<dim3(8, 256), 256, SMEM_BYTES>>>(-1, 0, 0,    512,  x, mu, ls, out); // -> buf0 (256 nodes)
    pair_kernel<false><<<dim3(8, 64),  256, SMEM_BYTES>>>( 0, 1, 768,  896,  x, mu, ls, out); // -> buf1 (64)
    pair_kernel<false><<<dim3(8, 16),  256, SMEM_BYTES>>>( 1, 0, 960,  992,  x, mu, ls, out); // -> buf0 (16)
    pair_kernel<false><<<dim3(8, 4),   256, SMEM_BYTES>>>( 0, 1, 1008, 1016, x, mu, ls, out); // -> buf1 (4)
    pair_kernel<false><<<dim3(8, 1),   256, SMEM_BYTES>>>( 1, 2, 1020, 1022, x, mu, ls, out); // -> dout (root)
}